// round 8
// baseline (speedup 1.0000x reference)
#include <cuda_runtime.h>
#include <cuda_bf16.h>
#include <cstdint>

// ============================================================================
// GraphCastProcessor — split-bf16 mma.sync GEMMs (R6 pipeline: cp.async A +
// cp.async.bulk B, double-buffered) + CSR gather edge pass (no atomics).
//   y1 = x@We[:256], y2 = x@We[256:512]
//   per dst node: agg = sum_e silu(LN(y1[dst]+y2[src]+ea@W3+b))  (edge_gather)
//   u = x@Wn1[:256] + agg@Wn1[256:] + b ; t = silu(LN(u))
//   x = x + t@Wn2 + b2
// ============================================================================

#define MAXN 40962
#define MAXD 163848
#define MAXNL 6

__device__ float g_bufA[MAXN * 256];
__device__ float g_bufB[MAXN * 256];
__device__ float g_y1  [MAXN * 256];
__device__ float g_y2  [MAXN * 256];
__device__ uint2 g_xs  [MAXN * 128];   // split activations {hi-pair, lo-pair}
__device__ uint2 g_aggs[MAXN * 128];
__device__ uint2 g_tmps[MAXN * 128];
// fragment-ordered weights: [layer][chunk][wn(4)][nt(8)][lane(32)] uint4
__device__ uint4 g_We [MAXNL * 32 * 1024];
__device__ uint4 g_Wn1[MAXNL * 32 * 1024];
__device__ uint4 g_Wn2[MAXNL * 16 * 1024];
// CSR (dst-sorted edges), rebuilt each launch
__device__ int g_cnt[MAXN];
__device__ int g_off[MAXN + 1];
__device__ int g_cur[MAXN];
__device__ int g_csr[MAXD];

// ---- dynamic smem layout (bytes) ----
#define SA_OFF    0                       // uint2 sA[2][64][10] = 10240
#define SB_OFF    10240                   // uint4 sB[2][1024]   -> 43008
#define SOUT_OFF  0                       // float sOut[64][260] = 66560 (aliases)
#define SBIAS_OFF 66560
#define SG_OFF    67584
#define SBV_OFF   68608
#define MBAR_OFF  69632                   // 2 x u64 mbarriers
#define SMEM_BYTES 69664

__device__ __forceinline__ float fast_silu(float y) {
    return __fdividef(y, 1.0f + __expf(-y));
}

__device__ __forceinline__ uint2 split_pack(float a, float b) {
    __nv_bfloat16 h0 = __float2bfloat16(a);
    __nv_bfloat16 h1 = __float2bfloat16(b);
    __nv_bfloat16 l0 = __float2bfloat16(a - __bfloat162float(h0));
    __nv_bfloat16 l1 = __float2bfloat16(b - __bfloat162float(h1));
    uint2 r;
    r.x = (uint32_t)__bfloat16_as_ushort(h0) | ((uint32_t)__bfloat16_as_ushort(h1) << 16);
    r.y = (uint32_t)__bfloat16_as_ushort(l0) | ((uint32_t)__bfloat16_as_ushort(l1) << 16);
    return r;
}

__device__ __forceinline__ void mma_bf16(float c[4], const uint32_t a[4],
                                         uint32_t b0, uint32_t b1) {
    asm volatile(
        "mma.sync.aligned.m16n8k16.row.col.f32.bf16.bf16.f32 "
        "{%0,%1,%2,%3}, {%4,%5,%6,%7}, {%8,%9}, {%0,%1,%2,%3};"
        : "+f"(c[0]), "+f"(c[1]), "+f"(c[2]), "+f"(c[3])
        : "r"(a[0]), "r"(a[1]), "r"(a[2]), "r"(a[3]), "r"(b0), "r"(b1));
}

__device__ __forceinline__ void cp16(uint32_t smem_dst, const void* gsrc) {
    asm volatile("cp.async.cg.shared.global [%0], [%1], 16;\n"
                 :: "r"(smem_dst), "l"(gsrc));
}
#define CP_COMMIT() asm volatile("cp.async.commit_group;\n" ::: "memory")
#define CP_WAIT(n)  asm volatile("cp.async.wait_group %0;\n" :: "n"(n) : "memory")

__device__ __forceinline__ void mbar_init(uint32_t mbar, uint32_t count) {
    asm volatile("mbarrier.init.shared.b64 [%0], %1;" :: "r"(mbar), "r"(count) : "memory");
}
__device__ __forceinline__ void mbar_expect_tx(uint32_t mbar, uint32_t bytes) {
    asm volatile("mbarrier.arrive.expect_tx.shared.b64 _, [%0], %1;"
                 :: "r"(mbar), "r"(bytes) : "memory");
}
__device__ __forceinline__ void mbar_wait(uint32_t mbar, uint32_t parity) {
    asm volatile(
        "{\n\t.reg .pred P1;\n\t"
        "WAIT_LOOP_%=:\n\t"
        "mbarrier.try_wait.parity.acquire.cta.shared::cta.b64 P1, [%0], %1, 0x989680;\n\t"
        "@P1 bra.uni WAIT_DONE_%=;\n\t"
        "bra.uni WAIT_LOOP_%=;\n\t"
        "WAIT_DONE_%=:\n\t}"
        :: "r"(mbar), "r"(parity) : "memory");
}
__device__ __forceinline__ void bulk_cp(uint32_t smem_dst, const void* gsrc,
                                        uint32_t bytes, uint32_t mbar) {
    asm volatile(
        "cp.async.bulk.shared::cta.global.mbarrier::complete_tx::bytes [%0], [%1], %2, [%3];"
        :: "r"(smem_dst), "l"(gsrc), "r"(bytes), "r"(mbar) : "memory");
}

// LN(256)+SiLU; row spread as 8 vals/lane (cols tx*4+j / 128+tx*4+j-4)
__device__ __forceinline__ void ln_silu_row(float v[8], int tx,
                                            const float* sG, const float* sB) {
    float s = v[0] + v[1] + v[2] + v[3] + v[4] + v[5] + v[6] + v[7];
#pragma unroll
    for (int o = 16; o > 0; o >>= 1) s += __shfl_xor_sync(0xffffffffu, s, o);
    float mean = s * (1.0f / 256.0f);
    float vs = 0.f;
#pragma unroll
    for (int j = 0; j < 8; j++) { float d = v[j] - mean; vs += d * d; }
#pragma unroll
    for (int o = 16; o > 0; o >>= 1) vs += __shfl_xor_sync(0xffffffffu, vs, o);
    float rstd = rsqrtf(vs * (1.0f / 256.0f) + 1e-5f);
#pragma unroll
    for (int j = 0; j < 8; j++) {
        int col = (j < 4) ? (tx * 4 + j) : (128 + tx * 4 + j - 4);
        float y = (v[j] - mean) * rstd * sG[col] + sB[col];
        v[j] = fast_silu(y);
    }
}

__device__ __forceinline__ void compute_chunk(const char* smraw, int buf,
                                              int wm, int wn, int lane,
                                              float acc[2][8][4]) {
    const uint2* sAp = (const uint2*)(smraw + SA_OFF + buf * 5120);
    const uint4* sBp = (const uint4*)(smraw + SB_OFF + buf * 16384);
    uint32_t ah[2][4], al[2][4];
    const int q = lane & 3;
#pragma unroll
    for (int mt = 0; mt < 2; mt++) {
        int r = wm * 32 + mt * 16 + (lane >> 2);
        uint2 v0 = sAp[r * 10 + q];
        uint2 v1 = sAp[(r + 8) * 10 + q];
        uint2 v2 = sAp[r * 10 + q + 4];
        uint2 v3 = sAp[(r + 8) * 10 + q + 4];
        ah[mt][0] = v0.x; ah[mt][1] = v1.x; ah[mt][2] = v2.x; ah[mt][3] = v3.x;
        al[mt][0] = v0.y; al[mt][1] = v1.y; al[mt][2] = v2.y; al[mt][3] = v3.y;
    }
#pragma unroll
    for (int nt = 0; nt < 8; nt++) {
        uint4 b = sBp[wn * 256 + nt * 32 + lane];
#pragma unroll
        for (int mt = 0; mt < 2; mt++) {
            mma_bf16(acc[mt][nt], ah[mt], b.x, b.y);  // hi*hi
            mma_bf16(acc[mt][nt], ah[mt], b.z, b.w);  // hi*lo
            mma_bf16(acc[mt][nt], al[mt], b.x, b.y);  // lo*hi
        }
    }
}

// pipeline: A via cp.async (gathered), B via cp.async.bulk (1 op/chunk)
template <typename FA>
__device__ __forceinline__ void gemm_pipeline(FA stageA, const uint4* __restrict__ Wp,
                                              char* smraw, uint32_t sbase, int tid,
                                              int wm, int wn, int lane, int chunks,
                                              float acc[2][8][4]) {
    const uint32_t mbar0 = sbase + MBAR_OFF;
    auto issueB = [&](int c, int buf) {
        if (tid == 0) {
            uint32_t mb = mbar0 + buf * 8;
            mbar_expect_tx(mb, 16384);
            bulk_cp(sbase + SB_OFF + buf * 16384, Wp + (size_t)c * 1024, 16384, mb);
        }
    };
    stageA(0, 0); CP_COMMIT(); issueB(0, 0);
#pragma unroll 1
    for (int c = 0; c < chunks; c++) {
        if (c + 1 < chunks) {
            stageA(c + 1, (c + 1) & 1); CP_COMMIT(); issueB(c + 1, (c + 1) & 1);
            CP_WAIT(1);
        } else {
            CP_WAIT(0);
        }
        mbar_wait(mbar0 + (c & 1) * 8, (c >> 1) & 1);
        __syncthreads();
        compute_chunk(smraw, c & 1, wm, wn, lane, acc);
        __syncthreads();
    }
}

__device__ __forceinline__ void acc_to_sout(char* smraw, int wm, int wn,
                                            int lane, float acc[2][8][4],
                                            const float* sBias) {
    float (*sOut)[260] = (float(*)[260])(smraw + SOUT_OFF);
#pragma unroll
    for (int mt = 0; mt < 2; mt++)
#pragma unroll
        for (int nt = 0; nt < 8; nt++) {
            int r0 = wm * 32 + mt * 16 + (lane >> 2);
            int c = wn * 64 + nt * 8 + 2 * (lane & 3);
            float b0 = sBias ? sBias[c] : 0.f;
            float b1 = sBias ? sBias[c + 1] : 0.f;
            sOut[r0][c]         = acc[mt][nt][0] + b0;
            sOut[r0][c + 1]     = acc[mt][nt][1] + b1;
            sOut[r0 + 8][c]     = acc[mt][nt][2] + b0;
            sOut[r0 + 8][c + 1] = acc[mt][nt][3] + b1;
        }
}

// ---------------------------------------------------------------------------
// packers + CSR build
// ---------------------------------------------------------------------------
__global__ void pack_w_frag(const float* __restrict__ W, uint4* __restrict__ out,
                            int Ksrc, int lstride, int C, int NL) {
    size_t idx = (size_t)blockIdx.x * blockDim.x + threadIdx.x;
    size_t total = (size_t)NL * C * 1024;
    if (idx >= total) return;
    int t = (int)(idx & 1023);
    int lane = t & 31, nt = (t >> 5) & 7, wn = t >> 8;
    int c = (int)((idx >> 10) % C);
    int l = (int)(idx / ((size_t)C * 1024));
    int n = wn * 64 + nt * 8 + (lane >> 2);
    int q = lane & 3;
    int kp0 = c * 8 + q, kp1 = c * 8 + q + 4;
    const float* Wl = W + (size_t)l * lstride * 256;
    float a0 = (2 * kp0     < Ksrc) ? Wl[(size_t)(2 * kp0)     * 256 + n] : 0.f;
    float a1 = (2 * kp0 + 1 < Ksrc) ? Wl[(size_t)(2 * kp0 + 1) * 256 + n] : 0.f;
    float b0 = (2 * kp1     < Ksrc) ? Wl[(size_t)(2 * kp1)     * 256 + n] : 0.f;
    float b1 = (2 * kp1 + 1 < Ksrc) ? Wl[(size_t)(2 * kp1 + 1) * 256 + n] : 0.f;
    uint2 p0 = split_pack(a0, a1);
    uint2 p1 = split_pack(b0, b1);
    out[idx] = make_uint4(p0.x, p1.x, p0.y, p1.y);
}

__global__ void convert_split(const float* __restrict__ in, uint2* __restrict__ out,
                              int n) {
    int i = blockIdx.x * blockDim.x + threadIdx.x;
    if (i < n) {
        float2 v = ((const float2*)in)[i];
        out[i] = split_pack(v.x, v.y);
    }
}

__global__ void zero_int(int* __restrict__ p, int n) {
    int i = blockIdx.x * blockDim.x + threadIdx.x;
    if (i < n) p[i] = 0;
}
__global__ void hist_k(const int* __restrict__ eidx, int* __restrict__ cnt, int D) {
    int e = blockIdx.x * blockDim.x + threadIdx.x;
    if (e < D) atomicAdd(&cnt[eidx[(size_t)D + e]], 1);
}
__global__ void scan_k(const int* __restrict__ cnt, int* __restrict__ off, int N) {
    __shared__ int sums[1025];
    int t = threadIdx.x;
    int len = (N + 1023) >> 10;
    int start = t * len;
    int end = start + len; if (end > N) end = N;
    int s = 0;
    for (int i = start; i < end; i++) s += cnt[i];
    sums[t] = s;
    __syncthreads();
    if (t == 0) {
        int run = 0;
        for (int i = 0; i < 1024; i++) { int v = sums[i]; sums[i] = run; run += v; }
        sums[1024] = run;
    }
    __syncthreads();
    int run = sums[t];
    for (int i = start; i < end; i++) { off[i] = run; run += cnt[i]; }
    if (t == 0) off[N] = sums[1024];
}
__global__ void scatter_k(const int* __restrict__ eidx, const int* __restrict__ off,
                          int* __restrict__ cur, int* __restrict__ csr, int D) {
    int e = blockIdx.x * blockDim.x + threadIdx.x;
    if (e >= D) return;
    int d = eidx[(size_t)D + e];
    int pos = off[d] + atomicAdd(&cur[d], 1);
    csr[pos] = e;
}

// ---------------------------------------------------------------------------
// y12 kernel: y = x @ We[half*256 : (half+1)*256]  (no bias), grid.y = half
// ---------------------------------------------------------------------------
__global__ __launch_bounds__(256, 2) void y12_kernel(
    const uint2* __restrict__ xs, const uint4* __restrict__ WpBase,
    float* __restrict__ y1, float* __restrict__ y2, int N) {
    extern __shared__ char smraw[];
    const int tid = threadIdx.x;
    const int lane = tid & 31, warp = tid >> 5;
    const int wm = warp >> 2, wn = warp & 3;
    const int n0 = blockIdx.x * 64;
    const int half = blockIdx.y;
    const uint32_t sbase = (uint32_t)__cvta_generic_to_shared(smraw);
    const int arow = tid >> 2, apart = tid & 3;
    int rowg = n0 + arow; if (rowg >= N) rowg = N - 1;

    if (tid == 0) { mbar_init(sbase + MBAR_OFF, 1); mbar_init(sbase + MBAR_OFF + 8, 1); }
    __syncthreads();

    const uint4* Wp = WpBase + (size_t)half * 16 * 1024;
    float* yout = half ? y2 : y1;

    float acc[2][8][4];
#pragma unroll
    for (int mt = 0; mt < 2; mt++)
#pragma unroll
        for (int nt = 0; nt < 8; nt++)
#pragma unroll
            for (int j = 0; j < 4; j++) acc[mt][nt][j] = 0.f;

    auto stageA = [&](int c, int buf) {
        const uint2* src = xs + (size_t)rowg * 128 + c * 8;
        cp16(sbase + SA_OFF + buf * 5120 + arow * 80 + apart * 16,
             (const char*)src + apart * 16);
    };
    gemm_pipeline(stageA, Wp, smraw, sbase, tid, wm, wn, lane, 16, acc);

    acc_to_sout(smraw, wm, wn, lane, acc, nullptr);
    __syncthreads();
    float (*sOut)[260] = (float(*)[260])(smraw + SOUT_OFF);
#pragma unroll 1
    for (int i = 0; i < 8; i++) {
        int r = i * 8 + warp;
        int row = n0 + r;
        if (row < N) {
            float* op = yout + (size_t)row * 256;
            *(float4*)(op + lane * 4)       = *(float4*)&sOut[r][lane * 4];
            *(float4*)(op + 128 + lane * 4) = *(float4*)&sOut[r][128 + lane * 4];
        }
    }
}

// ---------------------------------------------------------------------------
// Edge gather: one warp per dst node. agg_row = sum over incoming edges of
// silu(LN(y1[dst]+y2[src]+ea@W3+b)); write split pairs directly to aggs.
// Lane owns contiguous cols lane*8..lane*8+7.
// ---------------------------------------------------------------------------
__global__ __launch_bounds__(256) void edge_gather(
    const float* __restrict__ y1, const float* __restrict__ y2,
    const int* __restrict__ eidx, const float* __restrict__ ea,
    const int* __restrict__ csr, const int* __restrict__ off,
    const float* __restrict__ W3, const float* __restrict__ Wb,
    const float* __restrict__ gam, const float* __restrict__ bet,
    uint2* __restrict__ aggs, int N, int D) {
    const int lane = threadIdx.x & 31, warp = threadIdx.x >> 5;
    const int n = blockIdx.x * 8 + warp;
    if (n >= N) return;

    float w3r[4][8], biasr[8], gr[8], br[8];
#pragma unroll
    for (int j = 0; j < 8; j++) {
        int col = lane * 8 + j;
        biasr[j] = __ldg(Wb + col);
        gr[j] = __ldg(gam + col);
        br[j] = __ldg(bet + col);
#pragma unroll
        for (int k = 0; k < 4; k++) w3r[k][j] = __ldg(W3 + k * 256 + col);
    }

    const float* p1 = y1 + (size_t)n * 256;
    float y1v[8];
    *(float4*)&y1v[0] = *(const float4*)(p1 + lane * 8);
    *(float4*)&y1v[4] = *(const float4*)(p1 + lane * 8 + 4);

    int beg = __ldg(off + n);
    int end = __ldg(off + n + 1);

    float acc[8] = {0.f, 0.f, 0.f, 0.f, 0.f, 0.f, 0.f, 0.f};
    for (int i = beg; i < end; i++) {
        int e = __ldg(csr + i);
        int src = __ldg(eidx + e);
        const float* p2 = y2 + (size_t)src * 256;
        float v[8];
        *(float4*)&v[0] = *(const float4*)(p2 + lane * 8);
        *(float4*)&v[4] = *(const float4*)(p2 + lane * 8 + 4);
        float4 eav = *(const float4*)(ea + (size_t)e * 4);
#pragma unroll
        for (int j = 0; j < 8; j++) {
            float h = y1v[j] + v[j] + biasr[j];
            h = fmaf(eav.x, w3r[0][j], h);
            h = fmaf(eav.y, w3r[1][j], h);
            h = fmaf(eav.z, w3r[2][j], h);
            h = fmaf(eav.w, w3r[3][j], h);
            v[j] = h;
        }
        float s = v[0] + v[1] + v[2] + v[3] + v[4] + v[5] + v[6] + v[7];
#pragma unroll
        for (int o = 16; o > 0; o >>= 1) s += __shfl_xor_sync(0xffffffffu, s, o);
        float mean = s * (1.0f / 256.0f);
        float vs = 0.f;
#pragma unroll
        for (int j = 0; j < 8; j++) { float d = v[j] - mean; vs += d * d; }
#pragma unroll
        for (int o = 16; o > 0; o >>= 1) vs += __shfl_xor_sync(0xffffffffu, vs, o);
        float rstd = rsqrtf(vs * (1.0f / 256.0f) + 1e-5f);
#pragma unroll
        for (int j = 0; j < 8; j++)
            acc[j] += fast_silu((v[j] - mean) * rstd * gr[j] + br[j]);
    }

    uint2* op = aggs + (size_t)n * 128 + lane * 4;
#pragma unroll
    for (int jj = 0; jj < 4; jj++)
        op[jj] = split_pack(acc[2 * jj], acc[2 * jj + 1]);
}

// ---------------------------------------------------------------------------
// Node kernel 1: t = silu(LN(x@Wn1[:256] + agg@Wn1[256:] + b)) -> tmps (split)
// ---------------------------------------------------------------------------
__global__ __launch_bounds__(256, 2) void node1_kernel(
    const uint2* __restrict__ xs, const uint2* __restrict__ aggs,
    const uint4* __restrict__ Wp, const float* __restrict__ Wb,
    const float* __restrict__ gam, const float* __restrict__ bet,
    uint2* __restrict__ tmps, int N) {
    extern __shared__ char smraw[];
    float* sBias = (float*)(smraw + SBIAS_OFF);
    float* sG    = (float*)(smraw + SG_OFF);
    float* sBv   = (float*)(smraw + SBV_OFF);

    const int tid = threadIdx.x;
    const int lane = tid & 31, warp = tid >> 5;
    const int wm = warp >> 2, wn = warp & 3;
    const int n0 = blockIdx.x * 64;
    const uint32_t sbase = (uint32_t)__cvta_generic_to_shared(smraw);
    const int arow = tid >> 2, apart = tid & 3;

    sBias[tid] = Wb[tid]; sG[tid] = gam[tid]; sBv[tid] = bet[tid];
    if (tid == 0) { mbar_init(sbase + MBAR_OFF, 1); mbar_init(sbase + MBAR_OFF + 8, 1); }
    __syncthreads();

    int rowg = n0 + arow; if (rowg >= N) rowg = N - 1;

    float acc[2][8][4];
#pragma unroll
    for (int mt = 0; mt < 2; mt++)
#pragma unroll
        for (int nt = 0; nt < 8; nt++)
#pragma unroll
            for (int j = 0; j < 4; j++) acc[mt][nt][j] = 0.f;

    auto stageA = [&](int c, int buf) {
        const uint2* src = (c < 16 ? xs : aggs) + (size_t)rowg * 128 + (c & 15) * 8;
        cp16(sbase + SA_OFF + buf * 5120 + arow * 80 + apart * 16,
             (const char*)src + apart * 16);
    };
    gemm_pipeline(stageA, Wp, smraw, sbase, tid, wm, wn, lane, 32, acc);

    acc_to_sout(smraw, wm, wn, lane, acc, sBias);
    __syncthreads();
    float (*sOut)[260] = (float(*)[260])(smraw + SOUT_OFF);
#pragma unroll 1
    for (int i = 0; i < 8; i++) {
        int r = i * 8 + warp;
        float vv[8];
        *(float4*)&vv[0] = *(float4*)&sOut[r][lane * 4];
        *(float4*)&vv[4] = *(float4*)&sOut[r][128 + lane * 4];
        ln_silu_row(vv, lane, sG, sBv);
        int row = n0 + r;
        if (row < N) {
            uint2* op = tmps + (size_t)row * 128;
            op[lane * 2]          = split_pack(vv[0], vv[1]);
            op[lane * 2 + 1]      = split_pack(vv[2], vv[3]);
            op[64 + lane * 2]     = split_pack(vv[4], vv[5]);
            op[64 + lane * 2 + 1] = split_pack(vv[6], vv[7]);
        }
    }
}

// ---------------------------------------------------------------------------
// Node kernel 2: out = x + t@Wn2 + b2; also writes split xs for next layer
// ---------------------------------------------------------------------------
__global__ __launch_bounds__(256, 2) void node2_kernel(
    const uint2* __restrict__ tmps, const float* __restrict__ xres,
    const uint4* __restrict__ Wp, const float* __restrict__ Wb,
    float* __restrict__ out, uint2* __restrict__ xs_next, int N) {
    extern __shared__ char smraw[];
    float* sBias = (float*)(smraw + SBIAS_OFF);

    const int tid = threadIdx.x;
    const int lane = tid & 31, warp = tid >> 5;
    const int wm = warp >> 2, wn = warp & 3;
    const int n0 = blockIdx.x * 64;
    const uint32_t sbase = (uint32_t)__cvta_generic_to_shared(smraw);
    const int arow = tid >> 2, apart = tid & 3;

    sBias[tid] = Wb[tid];
    if (tid == 0) { mbar_init(sbase + MBAR_OFF, 1); mbar_init(sbase + MBAR_OFF + 8, 1); }
    __syncthreads();

    int rowg = n0 + arow; if (rowg >= N) rowg = N - 1;

    float acc[2][8][4];
#pragma unroll
    for (int mt = 0; mt < 2; mt++)
#pragma unroll
        for (int nt = 0; nt < 8; nt++)
#pragma unroll
            for (int j = 0; j < 4; j++) acc[mt][nt][j] = 0.f;

    auto stageA = [&](int c, int buf) {
        const uint2* src = tmps + (size_t)rowg * 128 + c * 8;
        cp16(sbase + SA_OFF + buf * 5120 + arow * 80 + apart * 16,
             (const char*)src + apart * 16);
    };
    gemm_pipeline(stageA, Wp, smraw, sbase, tid, wm, wn, lane, 16, acc);

    acc_to_sout(smraw, wm, wn, lane, acc, sBias);
    __syncthreads();
    float (*sOut)[260] = (float(*)[260])(smraw + SOUT_OFF);
#pragma unroll 1
    for (int i = 0; i < 8; i++) {
        int r = i * 8 + warp;
        int row = n0 + r;
        if (row < N) {
            const float* xr = xres + (size_t)row * 256;
            float4 lo = *(float4*)&sOut[r][lane * 4];
            float4 hi = *(float4*)&sOut[r][128 + lane * 4];
            float4 xlo = *(const float4*)(xr + lane * 4);
            float4 xhi = *(const float4*)(xr + 128 + lane * 4);
            lo.x += xlo.x; lo.y += xlo.y; lo.z += xlo.z; lo.w += xlo.w;
            hi.x += xhi.x; hi.y += xhi.y; hi.z += xhi.z; hi.w += xhi.w;
            float* op = out + (size_t)row * 256;
            *(float4*)(op + lane * 4) = lo;
            *(float4*)(op + 128 + lane * 4) = hi;
            uint2* xp = xs_next + (size_t)row * 128;
            xp[lane * 2]          = split_pack(lo.x, lo.y);
            xp[lane * 2 + 1]      = split_pack(lo.z, lo.w);
            xp[64 + lane * 2]     = split_pack(hi.x, hi.y);
            xp[64 + lane * 2 + 1] = split_pack(hi.z, hi.w);
        }
    }
}

// ---------------------------------------------------------------------------
extern "C" void kernel_launch(void* const* d_in, const int* in_sizes, int n_in,
                              void* d_out, int out_size) {
    const float* x_in  = (const float*)d_in[0];
    const int*   eidx  = (const int*)d_in[1];
    const float* ea    = (const float*)d_in[2];
    const float* We_w  = (const float*)d_in[3];
    const float* We_b  = (const float*)d_in[4];
    const float* g1    = (const float*)d_in[5];
    const float* b1    = (const float*)d_in[6];
    const float* Wn1_w = (const float*)d_in[7];
    const float* Wn1_b = (const float*)d_in[8];
    const float* g2    = (const float*)d_in[9];
    const float* b2    = (const float*)d_in[10];
    const float* Wn2_w = (const float*)d_in[11];
    const float* Wn2_b = (const float*)d_in[12];

    const int N  = in_sizes[0] / 256;
    const int D  = in_sizes[1] / 2;
    const int NL = in_sizes[4] / 256;

    float *bufA, *bufB, *y1p, *y2p;
    uint2 *xs, *aggs, *tmps;
    uint4 *wE, *wN1, *wN2;
    int *cnt, *off, *cur, *csr;
    cudaGetSymbolAddress((void**)&bufA, g_bufA);
    cudaGetSymbolAddress((void**)&bufB, g_bufB);
    cudaGetSymbolAddress((void**)&y1p,  g_y1);
    cudaGetSymbolAddress((void**)&y2p,  g_y2);
    cudaGetSymbolAddress((void**)&xs,   g_xs);
    cudaGetSymbolAddress((void**)&aggs, g_aggs);
    cudaGetSymbolAddress((void**)&tmps, g_tmps);
    cudaGetSymbolAddress((void**)&wE,   g_We);
    cudaGetSymbolAddress((void**)&wN1,  g_Wn1);
    cudaGetSymbolAddress((void**)&wN2,  g_Wn2);
    cudaGetSymbolAddress((void**)&cnt,  g_cnt);
    cudaGetSymbolAddress((void**)&off,  g_off);
    cudaGetSymbolAddress((void**)&cur,  g_cur);
    cudaGetSymbolAddress((void**)&csr,  g_csr);

    cudaFuncSetAttribute(y12_kernel,   cudaFuncAttributeMaxDynamicSharedMemorySize, SMEM_BYTES);
    cudaFuncSetAttribute(node1_kernel, cudaFuncAttributeMaxDynamicSharedMemorySize, SMEM_BYTES);
    cudaFuncSetAttribute(node2_kernel, cudaFuncAttributeMaxDynamicSharedMemorySize, SMEM_BYTES);

    // one-time packs + CSR build (deterministic, inside capture)
    {
        size_t t0 = (size_t)NL * 32 * 1024;
        pack_w_frag<<<(int)((t0 + 255) / 256), 256>>>(We_w, wE, 512, 516, 32, NL);
        pack_w_frag<<<(int)((t0 + 255) / 256), 256>>>(Wn1_w, wN1, 512, 512, 32, NL);
        size_t t2 = (size_t)NL * 16 * 1024;
        pack_w_frag<<<(int)((t2 + 255) / 256), 256>>>(Wn2_w, wN2, 256, 256, 16, NL);
        int nx = N * 128;
        convert_split<<<(nx + 255) / 256, 256>>>(x_in, xs, nx);
        zero_int<<<(N + 255) / 256, 256>>>(cnt, N);
        zero_int<<<(N + 255) / 256, 256>>>(cur, N);
        hist_k<<<(D + 255) / 256, 256>>>(eidx, cnt, D);
        scan_k<<<1, 1024>>>(cnt, off, N);
        scatter_k<<<(D + 255) / 256, 256>>>(eidx, off, cur, csr, D);
    }

    const int nblk_n = (N + 63) / 64;
    const int nblk_g = (N + 7) / 8;

    const float* xcur = x_in;
    for (int l = 0; l < NL; l++) {
        float* xnext = (l == NL - 1) ? (float*)d_out : ((l & 1) ? bufB : bufA);
        y12_kernel<<<dim3(nblk_n, 2), 256, SMEM_BYTES>>>(
            xs, wE + (size_t)l * 32 * 1024, y1p, y2p, N);
        edge_gather<<<nblk_g, 256>>>(
            y1p, y2p, eidx, ea, csr, off,
            We_w + (size_t)l * 516 * 256 + (size_t)512 * 256,
            We_b + (size_t)l * 256, g1 + (size_t)l * 256, b1 + (size_t)l * 256,
            aggs, N, D);
        node1_kernel<<<nblk_n, 256, SMEM_BYTES>>>(
            xs, aggs, wN1 + (size_t)l * 32 * 1024,
            Wn1_b + (size_t)l * 256, g2 + (size_t)l * 256, b2 + (size_t)l * 256,
            tmps, N);
        node2_kernel<<<nblk_n, 256, SMEM_BYTES>>>(
            tmps, xcur, wN2 + (size_t)l * 16 * 1024,
            Wn2_b + (size_t)l * 256, xnext, xs, N);
        xcur = xnext;
    }
}

// round 9
// speedup vs baseline: 1.4451x; 1.4451x over previous
#include <cuda_runtime.h>
#include <cuda_fp16.h>
#include <cstdint>

// ============================================================================
// GraphCastProcessor — fp16 weight-split mma.sync GEMMs (2 MMAs: xh*wh+xh*wl
// = xh*w, activation-rounding-only error ~2^-11) + atomic red.v4 edge pass.
//   y1 = x@We[:256], y2 = x@We[256:512]
//   h_e = y1[dst]+y2[src]+ea@W3+b ; msg = silu(LN(h)); agg += msg
//   u = x@Wn1[:256]+agg@Wn1[256:]+b ; t = silu(LN(u))
//   x = x + t@Wn2 + b2
// GEMM: block 64x256, 8 warps, K-superchunk 32 (2x k16), cp.async A +
// cp.async.bulk B (32KB/stage), double-buffered via mbarrier.
// ============================================================================

#define MAXN 40962
#define MAXD 163848
#define MAXNL 6

__device__ float g_bufA[MAXN * 256];
__device__ float g_bufB[MAXN * 256];
__device__ float g_agg [MAXN * 256];
__device__ float g_y1  [MAXN * 256];
__device__ float g_y2  [MAXN * 256];
__device__ uint32_t g_xs  [MAXN * 128];   // fp16x2 activations (hi only)
__device__ uint32_t g_aggs[MAXN * 128];
__device__ uint32_t g_tmps[MAXN * 128];
// fragment-ordered split weights: [layer][chunk16][wn(4)][nt(8)][lane(32)]
// uint4 = {hi_k0pair, hi_k1pair, lo_k0pair, lo_k1pair}
__device__ uint4 g_We [MAXNL * 32 * 1024];
__device__ uint4 g_Wn1[MAXNL * 32 * 1024];
__device__ uint4 g_Wn2[MAXNL * 16 * 1024];

// ---- dynamic smem layout (bytes) ----
#define SA_OFF    0                       // u32 sA[2][64][20] = 10240 (80B row)
#define SB_OFF    10240                   // uint4 sB[2][2048] = 65536 -> 75776
#define SOUT_OFF  0                       // float sOut[64][260] = 66560 (aliases)
#define SBIAS_OFF 75776
#define SG_OFF    76800
#define SBV_OFF   77824
#define MBAR_OFF  78848                   // 2 x u64
#define SMEM_BYTES 78880

__device__ __forceinline__ float fast_silu(float y) {
    return __fdividef(y, 1.0f + __expf(-y));
}

// activations: plain fp16 pair
__device__ __forceinline__ uint32_t packh(float a, float b) {
    __half2 h = __floats2half2_rn(a, b);
    return *(uint32_t*)&h;
}
// weights: hi/lo fp16 split pair
__device__ __forceinline__ uint2 wsplit(float a, float b) {
    __half h0 = __float2half_rn(a);
    __half h1 = __float2half_rn(b);
    __half l0 = __float2half_rn(a - __half2float(h0));
    __half l1 = __float2half_rn(b - __half2float(h1));
    uint2 r;
    r.x = (uint32_t)__half_as_ushort(h0) | ((uint32_t)__half_as_ushort(h1) << 16);
    r.y = (uint32_t)__half_as_ushort(l0) | ((uint32_t)__half_as_ushort(l1) << 16);
    return r;
}

__device__ __forceinline__ void mma_f16(float c[4], const uint32_t a[4],
                                        uint32_t b0, uint32_t b1) {
    asm volatile(
        "mma.sync.aligned.m16n8k16.row.col.f32.f16.f16.f32 "
        "{%0,%1,%2,%3}, {%4,%5,%6,%7}, {%8,%9}, {%0,%1,%2,%3};"
        : "+f"(c[0]), "+f"(c[1]), "+f"(c[2]), "+f"(c[3])
        : "r"(a[0]), "r"(a[1]), "r"(a[2]), "r"(a[3]), "r"(b0), "r"(b1));
}

__device__ __forceinline__ void red_v4(float* p, float a, float b, float c, float d) {
    asm volatile("red.global.add.v4.f32 [%0], {%1,%2,%3,%4};"
                 :: "l"(p), "f"(a), "f"(b), "f"(c), "f"(d) : "memory");
}

__device__ __forceinline__ void cp16(uint32_t smem_dst, const void* gsrc) {
    asm volatile("cp.async.cg.shared.global [%0], [%1], 16;\n"
                 :: "r"(smem_dst), "l"(gsrc));
}
#define CP_COMMIT() asm volatile("cp.async.commit_group;\n" ::: "memory")
#define CP_WAIT(n)  asm volatile("cp.async.wait_group %0;\n" :: "n"(n) : "memory")

__device__ __forceinline__ void mbar_init(uint32_t mbar, uint32_t count) {
    asm volatile("mbarrier.init.shared.b64 [%0], %1;" :: "r"(mbar), "r"(count) : "memory");
}
__device__ __forceinline__ void mbar_expect_tx(uint32_t mbar, uint32_t bytes) {
    asm volatile("mbarrier.arrive.expect_tx.shared.b64 _, [%0], %1;"
                 :: "r"(mbar), "r"(bytes) : "memory");
}
__device__ __forceinline__ void mbar_wait(uint32_t mbar, uint32_t parity) {
    asm volatile(
        "{\n\t.reg .pred P1;\n\t"
        "WAIT_LOOP_%=:\n\t"
        "mbarrier.try_wait.parity.acquire.cta.shared::cta.b64 P1, [%0], %1, 0x989680;\n\t"
        "@P1 bra.uni WAIT_DONE_%=;\n\t"
        "bra.uni WAIT_LOOP_%=;\n\t"
        "WAIT_DONE_%=:\n\t}"
        :: "r"(mbar), "r"(parity) : "memory");
}
__device__ __forceinline__ void bulk_cp(uint32_t smem_dst, const void* gsrc,
                                        uint32_t bytes, uint32_t mbar) {
    asm volatile(
        "cp.async.bulk.shared::cta.global.mbarrier::complete_tx::bytes [%0], [%1], %2, [%3];"
        :: "r"(smem_dst), "l"(gsrc), "r"(bytes), "r"(mbar) : "memory");
}

// LN(256)+SiLU; row spread as 8 vals/lane (cols tx*4+j / 128+tx*4+j-4)
__device__ __forceinline__ void ln_silu_row(float v[8], int tx,
                                            const float* sG, const float* sB) {
    float s = v[0] + v[1] + v[2] + v[3] + v[4] + v[5] + v[6] + v[7];
#pragma unroll
    for (int o = 16; o > 0; o >>= 1) s += __shfl_xor_sync(0xffffffffu, s, o);
    float mean = s * (1.0f / 256.0f);
    float vs = 0.f;
#pragma unroll
    for (int j = 0; j < 8; j++) { float d = v[j] - mean; vs += d * d; }
#pragma unroll
    for (int o = 16; o > 0; o >>= 1) vs += __shfl_xor_sync(0xffffffffu, vs, o);
    float rstd = rsqrtf(vs * (1.0f / 256.0f) + 1e-5f);
#pragma unroll
    for (int j = 0; j < 8; j++) {
        int col = (j < 4) ? (tx * 4 + j) : (128 + tx * 4 + j - 4);
        float y = (v[j] - mean) * rstd * sG[col] + sB[col];
        v[j] = fast_silu(y);
    }
}

// one K32 superchunk: two k16 halves, 2 MMAs each (xh*wh + xh*wl)
__device__ __forceinline__ void compute_schunk(const char* smraw, int buf,
                                               int wm, int wn, int lane,
                                               float acc[2][8][4]) {
    const uint32_t* sAp = (const uint32_t*)(smraw + SA_OFF + buf * 5120);
    const uint4* sBp = (const uint4*)(smraw + SB_OFF + buf * 32768);
    const int q = lane & 3;
#pragma unroll
    for (int h = 0; h < 2; h++) {
        uint32_t a[2][4];
#pragma unroll
        for (int mt = 0; mt < 2; mt++) {
            int r = wm * 32 + mt * 16 + (lane >> 2);
            a[mt][0] = sAp[r * 20 + h * 8 + q];
            a[mt][1] = sAp[(r + 8) * 20 + h * 8 + q];
            a[mt][2] = sAp[r * 20 + h * 8 + q + 4];
            a[mt][3] = sAp[(r + 8) * 20 + h * 8 + q + 4];
        }
#pragma unroll
        for (int nt = 0; nt < 8; nt++) {
            uint4 b = sBp[h * 1024 + wn * 256 + nt * 32 + lane];
#pragma unroll
            for (int mt = 0; mt < 2; mt++) {
                mma_f16(acc[mt][nt], a[mt], b.x, b.y);  // xh * w_hi
                mma_f16(acc[mt][nt], a[mt], b.z, b.w);  // xh * w_lo
            }
        }
    }
}

// pipeline over superchunks: A via cp.async, B via one 32KB bulk copy
template <typename FA>
__device__ __forceinline__ void gemm_pipeline(FA stageA, const uint4* __restrict__ Wp,
                                              char* smraw, uint32_t sbase, int tid,
                                              int wm, int wn, int lane, int schunks,
                                              float acc[2][8][4]) {
    const uint32_t mbar0 = sbase + MBAR_OFF;
    auto issueB = [&](int c, int buf) {
        if (tid == 0) {
            uint32_t mb = mbar0 + buf * 8;
            mbar_expect_tx(mb, 32768);
            bulk_cp(sbase + SB_OFF + buf * 32768, Wp + (size_t)c * 2048, 32768, mb);
        }
    };
    stageA(0, 0); CP_COMMIT(); issueB(0, 0);
#pragma unroll 1
    for (int c = 0; c < schunks; c++) {
        if (c + 1 < schunks) {
            stageA(c + 1, (c + 1) & 1); CP_COMMIT(); issueB(c + 1, (c + 1) & 1);
            CP_WAIT(1);
        } else {
            CP_WAIT(0);
        }
        mbar_wait(mbar0 + (c & 1) * 8, (c >> 1) & 1);
        __syncthreads();
        compute_schunk(smraw, c & 1, wm, wn, lane, acc);
        __syncthreads();
    }
}

__device__ __forceinline__ void acc_to_sout(char* smraw, int wm, int wn,
                                            int lane, float acc[2][8][4],
                                            const float* sBias) {
    float (*sOut)[260] = (float(*)[260])(smraw + SOUT_OFF);
#pragma unroll
    for (int mt = 0; mt < 2; mt++)
#pragma unroll
        for (int nt = 0; nt < 8; nt++) {
            int r0 = wm * 32 + mt * 16 + (lane >> 2);
            int c = wn * 64 + nt * 8 + 2 * (lane & 3);
            float b0 = sBias ? sBias[c] : 0.f;
            float b1 = sBias ? sBias[c + 1] : 0.f;
            sOut[r0][c]         = acc[mt][nt][0] + b0;
            sOut[r0][c + 1]     = acc[mt][nt][1] + b1;
            sOut[r0 + 8][c]     = acc[mt][nt][2] + b0;
            sOut[r0 + 8][c + 1] = acc[mt][nt][3] + b1;
        }
}

// ---------------------------------------------------------------------------
// packers
// ---------------------------------------------------------------------------
__global__ void pack_w_frag(const float* __restrict__ W, uint4* __restrict__ out,
                            int Ksrc, int lstride, int C, int NL) {
    size_t idx = (size_t)blockIdx.x * blockDim.x + threadIdx.x;
    size_t total = (size_t)NL * C * 1024;
    if (idx >= total) return;
    int t = (int)(idx & 1023);
    int lane = t & 31, nt = (t >> 5) & 7, wn = t >> 8;
    int c = (int)((idx >> 10) % C);
    int l = (int)(idx / ((size_t)C * 1024));
    int n = wn * 64 + nt * 8 + (lane >> 2);
    int q = lane & 3;
    int kp0 = c * 8 + q, kp1 = c * 8 + q + 4;
    const float* Wl = W + (size_t)l * lstride * 256;
    float a0 = (2 * kp0     < Ksrc) ? Wl[(size_t)(2 * kp0)     * 256 + n] : 0.f;
    float a1 = (2 * kp0 + 1 < Ksrc) ? Wl[(size_t)(2 * kp0 + 1) * 256 + n] : 0.f;
    float b0 = (2 * kp1     < Ksrc) ? Wl[(size_t)(2 * kp1)     * 256 + n] : 0.f;
    float b1 = (2 * kp1 + 1 < Ksrc) ? Wl[(size_t)(2 * kp1 + 1) * 256 + n] : 0.f;
    uint2 p0 = wsplit(a0, a1);
    uint2 p1 = wsplit(b0, b1);
    out[idx] = make_uint4(p0.x, p1.x, p0.y, p1.y);
}

__global__ void convert_h(const float* __restrict__ in, uint32_t* __restrict__ out,
                          int n) {
    int i = blockIdx.x * blockDim.x + threadIdx.x;
    if (i < n) {
        float2 v = ((const float2*)in)[i];
        out[i] = packh(v.x, v.y);
    }
}

__global__ void zero_kernel(float4* __restrict__ p, int n4) {
    int i = blockIdx.x * blockDim.x + threadIdx.x;
    if (i < n4) p[i] = make_float4(0.f, 0.f, 0.f, 0.f);
}

// ---------------------------------------------------------------------------
// y12 kernel: y = x @ We[half*256 : (half+1)*256]  (no bias), grid.y = half
// ---------------------------------------------------------------------------
__global__ __launch_bounds__(256, 2) void y12_kernel(
    const uint32_t* __restrict__ xs, const uint4* __restrict__ WpBase,
    float* __restrict__ y1, float* __restrict__ y2, int N) {
    extern __shared__ char smraw[];
    const int tid = threadIdx.x;
    const int lane = tid & 31, warp = tid >> 5;
    const int wm = warp >> 2, wn = warp & 3;
    const int n0 = blockIdx.x * 64;
    const int half = blockIdx.y;
    const uint32_t sbase = (uint32_t)__cvta_generic_to_shared(smraw);
    const int arow = tid >> 2, apart = tid & 3;
    int rowg = n0 + arow; if (rowg >= N) rowg = N - 1;

    if (tid == 0) { mbar_init(sbase + MBAR_OFF, 1); mbar_init(sbase + MBAR_OFF + 8, 1); }
    __syncthreads();

    const uint4* Wp = WpBase + (size_t)half * 16 * 1024;
    float* yout = half ? y2 : y1;

    float acc[2][8][4];
#pragma unroll
    for (int mt = 0; mt < 2; mt++)
#pragma unroll
        for (int nt = 0; nt < 8; nt++)
#pragma unroll
            for (int j = 0; j < 4; j++) acc[mt][nt][j] = 0.f;

    auto stageA = [&](int c, int buf) {
        const char* src = (const char*)(xs + (size_t)rowg * 128 + c * 16) + apart * 16;
        cp16(sbase + SA_OFF + buf * 5120 + arow * 80 + apart * 16, src);
    };
    gemm_pipeline(stageA, Wp, smraw, sbase, tid, wm, wn, lane, 8, acc);

    acc_to_sout(smraw, wm, wn, lane, acc, nullptr);
    __syncthreads();
    float (*sOut)[260] = (float(*)[260])(smraw + SOUT_OFF);
#pragma unroll 1
    for (int i = 0; i < 8; i++) {
        int r = i * 8 + warp;
        int row = n0 + r;
        if (row < N) {
            float* op = yout + (size_t)row * 256;
            *(float4*)(op + lane * 4)       = *(float4*)&sOut[r][lane * 4];
            *(float4*)(op + 128 + lane * 4) = *(float4*)&sOut[r][128 + lane * 4];
        }
    }
}

// ---------------------------------------------------------------------------
// Edge pass: h = y1[dst]+y2[src]+ea@W3+b; silu(LN(h)) -> red.v4 into agg
// one edge per warp, 8 edges per block (R6-verified)
// ---------------------------------------------------------------------------
__global__ __launch_bounds__(256) void edge_pass(
    const float* __restrict__ y1, const float* __restrict__ y2,
    const int* __restrict__ eidx, const float* __restrict__ ea,
    const float* __restrict__ W3, const float* __restrict__ Wb,
    const float* __restrict__ gam, const float* __restrict__ bet,
    float* __restrict__ agg, int D) {
    const int lane = threadIdx.x & 31, warp = threadIdx.x >> 5;
    const int e = blockIdx.x * 8 + warp;

    float w3r[4][8], biasr[8], gr[8], br[8];
#pragma unroll
    for (int j = 0; j < 8; j++) {
        int col = (j < 4) ? (lane * 4 + j) : (128 + lane * 4 + j - 4);
        biasr[j] = __ldg(Wb + col);
        gr[j] = __ldg(gam + col);
        br[j] = __ldg(bet + col);
#pragma unroll
        for (int k = 0; k < 4; k++) w3r[k][j] = __ldg(W3 + k * 256 + col);
    }
    if (e >= D) return;

    int src = __ldg(eidx + e);
    int dst = __ldg(eidx + (size_t)D + e);
    const float* p1 = y1 + (size_t)dst * 256;
    const float* p2 = y2 + (size_t)src * 256;
    float4 a0 = *(const float4*)(p1 + lane * 4);
    float4 a1 = *(const float4*)(p1 + 128 + lane * 4);
    float4 c0 = *(const float4*)(p2 + lane * 4);
    float4 c1 = *(const float4*)(p2 + 128 + lane * 4);
    float4 eav = *(const float4*)(ea + (size_t)e * 4);

    float v[8];
    v[0] = a0.x + c0.x; v[1] = a0.y + c0.y; v[2] = a0.z + c0.z; v[3] = a0.w + c0.w;
    v[4] = a1.x + c1.x; v[5] = a1.y + c1.y; v[6] = a1.z + c1.z; v[7] = a1.w + c1.w;
#pragma unroll
    for (int j = 0; j < 8; j++) {
        float h = v[j] + biasr[j];
        h = fmaf(eav.x, w3r[0][j], h);
        h = fmaf(eav.y, w3r[1][j], h);
        h = fmaf(eav.z, w3r[2][j], h);
        h = fmaf(eav.w, w3r[3][j], h);
        v[j] = h;
    }
    float s = v[0] + v[1] + v[2] + v[3] + v[4] + v[5] + v[6] + v[7];
#pragma unroll
    for (int o = 16; o > 0; o >>= 1) s += __shfl_xor_sync(0xffffffffu, s, o);
    float mean = s * (1.0f / 256.0f);
    float vs = 0.f;
#pragma unroll
    for (int j = 0; j < 8; j++) { float d = v[j] - mean; vs += d * d; }
#pragma unroll
    for (int o = 16; o > 0; o >>= 1) vs += __shfl_xor_sync(0xffffffffu, vs, o);
    float rstd = rsqrtf(vs * (1.0f / 256.0f) + 1e-5f);

    float m[8];
#pragma unroll
    for (int j = 0; j < 8; j++)
        m[j] = fast_silu((v[j] - mean) * rstd * gr[j] + br[j]);

    float* ag = agg + (size_t)dst * 256;
    red_v4(ag + lane * 4,       m[0], m[1], m[2], m[3]);
    red_v4(ag + 128 + lane * 4, m[4], m[5], m[6], m[7]);
}

// ---------------------------------------------------------------------------
// Node kernel 1: t = silu(LN(x@Wn1[:256] + agg@Wn1[256:] + b)) -> tmps (fp16)
// ---------------------------------------------------------------------------
__global__ __launch_bounds__(256, 2) void node1_kernel(
    const uint32_t* __restrict__ xs, const uint32_t* __restrict__ aggs,
    const uint4* __restrict__ Wp, const float* __restrict__ Wb,
    const float* __restrict__ gam, const float* __restrict__ bet,
    uint32_t* __restrict__ tmps, int N) {
    extern __shared__ char smraw[];
    float* sBias = (float*)(smraw + SBIAS_OFF);
    float* sG    = (float*)(smraw + SG_OFF);
    float* sBv   = (float*)(smraw + SBV_OFF);

    const int tid = threadIdx.x;
    const int lane = tid & 31, warp = tid >> 5;
    const int wm = warp >> 2, wn = warp & 3;
    const int n0 = blockIdx.x * 64;
    const uint32_t sbase = (uint32_t)__cvta_generic_to_shared(smraw);
    const int arow = tid >> 2, apart = tid & 3;

    sBias[tid] = Wb[tid]; sG[tid] = gam[tid]; sBv[tid] = bet[tid];
    if (tid == 0) { mbar_init(sbase + MBAR_OFF, 1); mbar_init(sbase + MBAR_OFF + 8, 1); }
    __syncthreads();

    int rowg = n0 + arow; if (rowg >= N) rowg = N - 1;

    float acc[2][8][4];
#pragma unroll
    for (int mt = 0; mt < 2; mt++)
#pragma unroll
        for (int nt = 0; nt < 8; nt++)
#pragma unroll
            for (int j = 0; j < 4; j++) acc[mt][nt][j] = 0.f;

    auto stageA = [&](int c, int buf) {
        const uint32_t* bA = (c < 8) ? xs : aggs;
        const char* src = (const char*)(bA + (size_t)rowg * 128 + (c & 7) * 16) + apart * 16;
        cp16(sbase + SA_OFF + buf * 5120 + arow * 80 + apart * 16, src);
    };
    gemm_pipeline(stageA, Wp, smraw, sbase, tid, wm, wn, lane, 16, acc);

    acc_to_sout(smraw, wm, wn, lane, acc, sBias);
    __syncthreads();
    float (*sOut)[260] = (float(*)[260])(smraw + SOUT_OFF);
#pragma unroll 1
    for (int i = 0; i < 8; i++) {
        int r = i * 8 + warp;
        float vv[8];
        *(float4*)&vv[0] = *(float4*)&sOut[r][lane * 4];
        *(float4*)&vv[4] = *(float4*)&sOut[r][128 + lane * 4];
        ln_silu_row(vv, lane, sG, sBv);
        int row = n0 + r;
        if (row < N) {
            uint32_t* op = tmps + (size_t)row * 128;
            op[lane * 2]          = packh(vv[0], vv[1]);
            op[lane * 2 + 1]      = packh(vv[2], vv[3]);
            op[64 + lane * 2]     = packh(vv[4], vv[5]);
            op[64 + lane * 2 + 1] = packh(vv[6], vv[7]);
        }
    }
}

// ---------------------------------------------------------------------------
// Node kernel 2: out = x + t@Wn2 + b2; also writes fp16 xs for next layer
// ---------------------------------------------------------------------------
__global__ __launch_bounds__(256, 2) void node2_kernel(
    const uint32_t* __restrict__ tmps, const float* __restrict__ xres,
    const uint4* __restrict__ Wp, const float* __restrict__ Wb,
    float* __restrict__ out, uint32_t* __restrict__ xs_next, int N) {
    extern __shared__ char smraw[];
    float* sBias = (float*)(smraw + SBIAS_OFF);

    const int tid = threadIdx.x;
    const int lane = tid & 31, warp = tid >> 5;
    const int wm = warp >> 2, wn = warp & 3;
    const int n0 = blockIdx.x * 64;
    const uint32_t sbase = (uint32_t)__cvta_generic_to_shared(smraw);
    const int arow = tid >> 2, apart = tid & 3;

    sBias[tid] = Wb[tid];
    if (tid == 0) { mbar_init(sbase + MBAR_OFF, 1); mbar_init(sbase + MBAR_OFF + 8, 1); }
    __syncthreads();

    int rowg = n0 + arow; if (rowg >= N) rowg = N - 1;

    float acc[2][8][4];
#pragma unroll
    for (int mt = 0; mt < 2; mt++)
#pragma unroll
        for (int nt = 0; nt < 8; nt++)
#pragma unroll
            for (int j = 0; j < 4; j++) acc[mt][nt][j] = 0.f;

    auto stageA = [&](int c, int buf) {
        const char* src = (const char*)(tmps + (size_t)rowg * 128 + c * 16) + apart * 16;
        cp16(sbase + SA_OFF + buf * 5120 + arow * 80 + apart * 16, src);
    };
    gemm_pipeline(stageA, Wp, smraw, sbase, tid, wm, wn, lane, 8, acc);

    acc_to_sout(smraw, wm, wn, lane, acc, sBias);
    __syncthreads();
    float (*sOut)[260] = (float(*)[260])(smraw + SOUT_OFF);
#pragma unroll 1
    for (int i = 0; i < 8; i++) {
        int r = i * 8 + warp;
        int row = n0 + r;
        if (row < N) {
            const float* xr = xres + (size_t)row * 256;
            float4 lo = *(float4*)&sOut[r][lane * 4];
            float4 hi = *(float4*)&sOut[r][128 + lane * 4];
            float4 xlo = *(const float4*)(xr + lane * 4);
            float4 xhi = *(const float4*)(xr + 128 + lane * 4);
            lo.x += xlo.x; lo.y += xlo.y; lo.z += xlo.z; lo.w += xlo.w;
            hi.x += xhi.x; hi.y += xhi.y; hi.z += xhi.z; hi.w += xhi.w;
            float* op = out + (size_t)row * 256;
            *(float4*)(op + lane * 4) = lo;
            *(float4*)(op + 128 + lane * 4) = hi;
            uint32_t* xp = xs_next + (size_t)row * 128;
            xp[lane * 2]          = packh(lo.x, lo.y);
            xp[lane * 2 + 1]      = packh(lo.z, lo.w);
            xp[64 + lane * 2]     = packh(hi.x, hi.y);
            xp[64 + lane * 2 + 1] = packh(hi.z, hi.w);
        }
    }
}

// ---------------------------------------------------------------------------
extern "C" void kernel_launch(void* const* d_in, const int* in_sizes, int n_in,
                              void* d_out, int out_size) {
    const float* x_in  = (const float*)d_in[0];
    const int*   eidx  = (const int*)d_in[1];
    const float* ea    = (const float*)d_in[2];
    const float* We_w  = (const float*)d_in[3];
    const float* We_b  = (const float*)d_in[4];
    const float* g1    = (const float*)d_in[5];
    const float* b1    = (const float*)d_in[6];
    const float* Wn1_w = (const float*)d_in[7];
    const float* Wn1_b = (const float*)d_in[8];
    const float* g2    = (const float*)d_in[9];
    const float* b2    = (const float*)d_in[10];
    const float* Wn2_w = (const float*)d_in[11];
    const float* Wn2_b = (const float*)d_in[12];

    const int N  = in_sizes[0] / 256;
    const int D  = in_sizes[1] / 2;
    const int NL = in_sizes[4] / 256;

    float *bufA, *bufB, *aggp, *y1p, *y2p;
    uint32_t *xs, *aggs, *tmps;
    uint4 *wE, *wN1, *wN2;
    cudaGetSymbolAddress((void**)&bufA, g_bufA);
    cudaGetSymbolAddress((void**)&bufB, g_bufB);
    cudaGetSymbolAddress((void**)&aggp, g_agg);
    cudaGetSymbolAddress((void**)&y1p,  g_y1);
    cudaGetSymbolAddress((void**)&y2p,  g_y2);
    cudaGetSymbolAddress((void**)&xs,   g_xs);
    cudaGetSymbolAddress((void**)&aggs, g_aggs);
    cudaGetSymbolAddress((void**)&tmps, g_tmps);
    cudaGetSymbolAddress((void**)&wE,   g_We);
    cudaGetSymbolAddress((void**)&wN1,  g_Wn1);
    cudaGetSymbolAddress((void**)&wN2,  g_Wn2);

    cudaFuncSetAttribute(y12_kernel,   cudaFuncAttributeMaxDynamicSharedMemorySize, SMEM_BYTES);
    cudaFuncSetAttribute(node1_kernel, cudaFuncAttributeMaxDynamicSharedMemorySize, SMEM_BYTES);
    cudaFuncSetAttribute(node2_kernel, cudaFuncAttributeMaxDynamicSharedMemorySize, SMEM_BYTES);

    // one-time packs (deterministic, inside capture)
    {
        size_t t0 = (size_t)NL * 32 * 1024;
        pack_w_frag<<<(int)((t0 + 255) / 256), 256>>>(We_w, wE, 512, 516, 32, NL);
        pack_w_frag<<<(int)((t0 + 255) / 256), 256>>>(Wn1_w, wN1, 512, 512, 32, NL);
        size_t t2 = (size_t)NL * 16 * 1024;
        pack_w_frag<<<(int)((t2 + 255) / 256), 256>>>(Wn2_w, wN2, 256, 256, 16, NL);
        int nx = N * 128;
        convert_h<<<(nx + 255) / 256, 256>>>(x_in, xs, nx);
    }

    const int nblk_n = (N + 63) / 64;
    const int nblk_e = (D + 7) / 8;
    const int n4 = (N * 256) / 4;
    const int zblk = (n4 + 255) / 256;
    const int ncv = N * 128;
    const int cvblk = (ncv + 255) / 256;

    const float* xcur = x_in;
    for (int l = 0; l < NL; l++) {
        float* xnext = (l == NL - 1) ? (float*)d_out : ((l & 1) ? bufB : bufA);
        zero_kernel<<<zblk, 256>>>((float4*)aggp, n4);
        y12_kernel<<<dim3(nblk_n, 2), 256, SMEM_BYTES>>>(
            xs, wE + (size_t)l * 32 * 1024, y1p, y2p, N);
        edge_pass<<<nblk_e, 256>>>(
            y1p, y2p, eidx, ea,
            We_w + (size_t)l * 516 * 256 + (size_t)512 * 256,
            We_b + (size_t)l * 256, g1 + (size_t)l * 256, b1 + (size_t)l * 256,
            aggp, D);
        convert_h<<<cvblk, 256>>>(aggp, aggs, ncv);
        node1_kernel<<<nblk_n, 256, SMEM_BYTES>>>(
            xs, aggs, wN1 + (size_t)l * 32 * 1024,
            Wn1_b + (size_t)l * 256, g2 + (size_t)l * 256, b2 + (size_t)l * 256,
            tmps, N);
        node2_kernel<<<nblk_n, 256, SMEM_BYTES>>>(
            tmps, xcur, wN2 + (size_t)l * 16 * 1024,
            Wn2_b + (size_t)l * 256, xnext, xs, N);
        xcur = xnext;
    }
}